// round 3
// baseline (speedup 1.0000x reference)
#include <cuda_runtime.h>
#include <math.h>

#define NS 1024
#define HD 256
#define XD 128
#define SP 35   // k_pair smem row stride in float2 units (70 words: 16-row strided LDS.64 conflict-free)

// scratch (device globals: no allocation allowed)
__device__ float g_xp[NS * HD];    // x @ Wx
__device__ float g_yp[NS * HD];    // y @ Wy + b1
__device__ double g_pe[1024];      // per-block exp-sum partials
__device__ double g_pd[1024];      // per-block diag partials
__device__ unsigned int g_cnt;

typedef unsigned long long u64;

__device__ __forceinline__ u64 pk2(float a, float b) {
    u64 r; asm("mov.b64 %0, {%1, %2};" : "=l"(r) : "f"(a), "f"(b)); return r;
}
__device__ __forceinline__ void up2(u64 v, float& a, float& b) {
    asm("mov.b64 {%0, %1}, %2;" : "=f"(a), "=f"(b) : "l"(v));
}
__device__ __forceinline__ u64 add2(u64 a, u64 b) {
    u64 r; asm("add.rn.f32x2 %0, %1, %2;" : "=l"(r) : "l"(a), "l"(b)); return r;
}
__device__ __forceinline__ u64 fma2(u64 a, u64 b, u64 c) {
    u64 r; asm("fma.rn.f32x2 %0, %1, %2, %3;" : "=l"(r) : "l"(a), "l"(b), "l"(c)); return r;
}

// xp = x @ W1[:128]; yp = y @ W1[128:] + b1.
// 256 blocks x 256 threads; 8 rows per block; thread = one output column.
__global__ void __launch_bounds__(256) k_gemm(
    const float* __restrict__ x, const float* __restrict__ y,
    const float* __restrict__ W1, const float* __restrict__ b1)
{
    if (blockIdx.x == 0 && threadIdx.x == 0) g_cnt = 0u;

    __shared__ __align__(16) float xs[128 * 10];  // [k][r], stride 10 (u64-aligned row pairs)
    int b = blockIdx.x;
    int isY = b >> 7;
    int row0 = (b & 127) << 3;
    const float* src = isY ? y : x;
    const float* W = W1 + isY * (XD * HD);
    int t = threadIdx.x;

    #pragma unroll
    for (int p = 0; p < 4; p++) {
        int idx = t + p * 256;          // 0..1023
        int r = idx >> 7, k = idx & 127;
        xs[k * 10 + r] = src[(row0 + r) * XD + k];
    }
    __syncthreads();

    u64 acc[4];
    #pragma unroll
    for (int m = 0; m < 4; m++) acc[m] = 0ull;

    #pragma unroll 8
    for (int k = 0; k < 128; k++) {
        float w = W[k * HD + t];
        u64 wd = pk2(w, w);
        #pragma unroll
        for (int m = 0; m < 4; m++)
            acc[m] = fma2(*(const u64*)&xs[k * 10 + 2 * m], wd, acc[m]);
    }

    float bias = isY ? b1[t] : 0.0f;
    float* dst = isY ? g_yp : g_xp;
    #pragma unroll
    for (int m = 0; m < 4; m++) {
        float v0, v1; up2(acc[m], v0, v1);
        dst[(row0 + 2 * m)     * HD + t] = v0 + bias;
        dst[(row0 + 2 * m + 1) * HD + t] = v1 + bias;
    }
}

// Pairwise kernel: 32x32 tile per CTA, 128 threads, 8 pairs/thread (4i x 2j).
// 1024 CTAs -> single resident wave at 8 CTAs/SM. Last block folds the final scalar.
__global__ void __launch_bounds__(128, 8) k_pair(
    const float* __restrict__ W2, const float* __restrict__ b2,
    float* __restrict__ out)
{
    __shared__ __align__(16) float2 xsh[32 * SP];  // j rows
    __shared__ __align__(16) float2 ysh[32 * SP];  // i rows
    __shared__ __align__(16) float2 wsh[128];      // all 256 W2 values
    __shared__ float rr[8];
    __shared__ int flag_sh;

    int t = threadIdx.x;
    int tx = t & 15, ty = t >> 4;                 // ty 0..7
    int jT = blockIdx.x << 5, iT = blockIdx.y << 5;

    wsh[t] = ((const float2*)W2)[t];              // 128 threads load all 128 f2

    const float4* gx = (const float4*)g_xp;       // 64 f4 per 256-float row
    const float4* gy = (const float4*)g_yp;

    u64 acc[8];
    #pragma unroll
    for (int p = 0; p < 8; p++) acc[p] = 0ull;

    #pragma unroll 1
    for (int ch = 0; ch < 4; ch++) {
        __syncthreads();  // previous chunk reads done (and wsh visible on first pass)
        // fill: 32 rows x 16 f4 per array; 4 f4 per thread per array
        #pragma unroll
        for (int p = 0; p < 4; p++) {
            int idx = t + p * 128;                // 0..511
            int row = idx >> 4, c4 = idx & 15;
            float4 vx = gx[(jT + row) * 64 + ch * 16 + c4];
            float4 vy = gy[(iT + row) * 64 + ch * 16 + c4];
            xsh[row * SP + 2 * c4]     = make_float2(vx.x, vx.y);
            xsh[row * SP + 2 * c4 + 1] = make_float2(vx.z, vx.w);
            ysh[row * SP + 2 * c4]     = make_float2(vy.x, vy.y);
            ysh[row * SP + 2 * c4 + 1] = make_float2(vy.z, vy.w);
        }
        __syncthreads();

        #pragma unroll
        for (int k2 = 0; k2 < 32; k2++) {         // 2 k-values per iter
            u64 w = *(const u64*)&wsh[ch * 32 + k2];
            u64 xv0 = *(const u64*)&xsh[tx * SP + k2];
            u64 xv1 = *(const u64*)&xsh[(tx + 16) * SP + k2];
            u64 yv[4];
            #pragma unroll
            for (int b4 = 0; b4 < 4; b4++)
                yv[b4] = *(const u64*)&ysh[(ty + 8 * b4) * SP + k2];
            #pragma unroll
            for (int b4 = 0; b4 < 4; b4++) {
                u64 s0 = add2(xv0, yv[b4]);
                float l0, h0; up2(s0, l0, h0);
                l0 = fmaxf(l0, 0.0f); h0 = fmaxf(h0, 0.0f);
                acc[b4 * 2]     = fma2(pk2(l0, h0), w, acc[b4 * 2]);
                u64 s1 = add2(xv1, yv[b4]);
                float l1, h1; up2(s1, l1, h1);
                l1 = fmaxf(l1, 0.0f); h1 = fmaxf(h1, 0.0f);
                acc[b4 * 2 + 1] = fma2(pk2(l1, h1), w, acc[b4 * 2 + 1]);
            }
        }
    }

    // epilogue: per-pair dot -> exp-sum + diagonal capture
    float le = 0.0f, ld = 0.0f;
    #pragma unroll
    for (int b4 = 0; b4 < 4; b4++) {
        #pragma unroll
        for (int a = 0; a < 2; a++) {
            float lo, hi; up2(acc[b4 * 2 + a], lo, hi);
            float s = lo + hi;
            le += __expf(s);
            if (iT + ty + 8 * b4 == jT + tx + 16 * a) ld += s;
        }
    }

    #pragma unroll
    for (int o = 16; o > 0; o >>= 1) {
        le += __shfl_xor_sync(0xffffffffu, le, o);
        ld += __shfl_xor_sync(0xffffffffu, ld, o);
    }
    int wid = t >> 5, lane = t & 31;
    if (lane == 0) { rr[wid] = le; rr[4 + wid] = ld; }
    __syncthreads();
    if (t == 0) {
        float se = 0.0f, sd = 0.0f;
        #pragma unroll
        for (int w2i = 0; w2i < 4; w2i++) { se += rr[w2i]; sd += rr[4 + w2i]; }
        int bid = blockIdx.y * 32 + blockIdx.x;
        g_pe[bid] = (double)se;
        g_pd[bid] = (double)sd;
        __threadfence();
        unsigned int c = atomicAdd(&g_cnt, 1u);
        flag_sh = (c == 1023u) ? 1 : 0;
    }
    __syncthreads();

    if (flag_sh) {
        // last block: reduce the 1024 partials and emit the scalar
        __threadfence();
        double se = 0.0, sd = 0.0;
        #pragma unroll
        for (int p = 0; p < 8; p++) {
            int i = t + p * 128;
            se += g_pe[i];
            sd += g_pd[i];
        }
        #pragma unroll
        for (int o = 16; o > 0; o >>= 1) {
            se += __shfl_xor_sync(0xffffffffu, se, o);
            sd += __shfl_xor_sync(0xffffffffu, sd, o);
        }
        __shared__ double dr[8];
        if (lane == 0) { dr[wid] = se; dr[4 + wid] = sd; }
        __syncthreads();
        if (t == 0) {
            double tse = dr[0] + dr[1] + dr[2] + dr[3];
            double tsd = dr[4] + dr[5] + dr[6] + dr[7];
            double bb = (double)b2[0];
            double lb = tsd / (double)NS + bb
                      - exp(bb - 1.0) * tse / ((double)NS * (double)NS);
            out[0] = (float)lb;
        }
    }
}

extern "C" void kernel_launch(void* const* d_in, const int* in_sizes, int n_in,
                              void* d_out, int out_size)
{
    (void)in_sizes; (void)n_in; (void)out_size;
    const float* x  = (const float*)d_in[0];
    const float* y  = (const float*)d_in[1];
    const float* W1 = (const float*)d_in[2];
    const float* b1 = (const float*)d_in[3];
    const float* W2 = (const float*)d_in[4];
    const float* b2 = (const float*)d_in[5];

    k_gemm<<<256, 256>>>(x, y, W1, b1);
    k_pair<<<dim3(32, 32), 128>>>(W2, b2, (float*)d_out);
}